// round 5
// baseline (speedup 1.0000x reference)
#include <cuda_runtime.h>
#include <cstdint>

#define BB 16
#define HH 8
#define GG 1024
#define II 256
#define DD 64
#define NEG_INF (-1e30f)

#define QT 128          // q rows per CTA
#define KT 64           // k cols per tile
// dynamic smem word offsets
#define OFF_Q 0         // Qs2 interleaved: [dp][i*2+p], 32*256 = 8192 words
#define OFF_K 8192      // Ks2 interleaved: [dp][j*2+p], 32*128 = 4096 words
#define OFF_V 12288     // Vs natural: [j][n], 64*64 = 4096 words
#define OFF_P 16384     // Pt: [j][i], stride 130, 64*130 = 8320 words
#define PT_STRIDE 130
#define SM_WORDS 24704  // 98816 bytes

typedef unsigned long long ull;

// scratch for q, k, v projections: [b][h][g][d]
__device__ float g_q[BB*HH*GG*DD];
__device__ float g_k[BB*HH*GG*DD];
__device__ float g_v[BB*HH*GG*DD];

// ---- packed f32x2 helpers (sm_100+) --------------------------------------
__device__ __forceinline__ ull f2pack(float lo, float hi) {
    ull r;
    asm("mov.b64 %0, {%1, %2};" : "=l"(r) : "f"(lo), "f"(hi));
    return r;
}
__device__ __forceinline__ void f2unpack(ull v, float& lo, float& hi) {
    asm("mov.b64 {%0, %1}, %2;" : "=f"(lo), "=f"(hi) : "l"(v));
}
__device__ __forceinline__ void ffma2(ull& d, ull a, ull b) {
    asm("fma.rn.f32x2 %0, %1, %2, %0;" : "+l"(d) : "l"(a), "l"(b));
}
__device__ __forceinline__ ull fmul2(ull a, ull b) {
    ull r;
    asm("mul.rn.f32x2 %0, %1, %2;" : "=l"(r) : "l"(a), "l"(b));
    return r;
}

// ---------------------------------------------------------------------------
// Projection (unchanged from R2): C[16384x64] = A[16384x256] @ W[h][256x64]
// ---------------------------------------------------------------------------
__global__ __launch_bounds__(256) void proj_kernel(
    const float* __restrict__ A,
    const float* __restrict__ W,
    int which)
{
    __shared__ float As[32][132];
    __shared__ float Bs[32][64];

    float* outbuf = (which == 0) ? g_q : (which == 1) ? g_k : g_v;

    const int hh = blockIdx.y;
    const int r0 = blockIdx.x * 128;
    const float* Wh = W + hh * II * DD;

    const int tid = threadIdx.x;
    const int tm = tid >> 4;
    const int tn = tid & 15;

    ull acc2[4][4];
#pragma unroll
    for (int i = 0; i < 4; i++)
#pragma unroll
        for (int j = 0; j < 4; j++) acc2[i][j] = 0ull;

    for (int k0 = 0; k0 < II; k0 += 32) {
#pragma unroll
        for (int t = 0; t < 4; t++) {
            int id  = tid + t * 256;
            int row = id >> 3;
            int c4  = (id & 7) << 2;
            float4 v = *(const float4*)(A + (r0 + row) * II + k0 + c4);
            As[c4 + 0][row] = v.x;
            As[c4 + 1][row] = v.y;
            As[c4 + 2][row] = v.z;
            As[c4 + 3][row] = v.w;
        }
#pragma unroll
        for (int t = 0; t < 2; t++) {
            int id  = tid + t * 256;
            int row = id >> 4;
            int c4  = (id & 15) << 2;
            *(float4*)(&Bs[row][c4]) = *(const float4*)(Wh + (k0 + row) * DD + c4);
        }
        __syncthreads();

#pragma unroll 8
        for (int kk = 0; kk < 32; kk++) {
            ulonglong2 a01 = *(const ulonglong2*)(&As[kk][tm * 8]);
            ulonglong2 a23 = *(const ulonglong2*)(&As[kk][tm * 8 + 4]);
            float4 b4 = *(const float4*)(&Bs[kk][tn * 4]);
            ull bd0 = f2pack(b4.x, b4.x);
            ull bd1 = f2pack(b4.y, b4.y);
            ull bd2 = f2pack(b4.z, b4.z);
            ull bd3 = f2pack(b4.w, b4.w);
            ffma2(acc2[0][0], a01.x, bd0); ffma2(acc2[0][1], a01.x, bd1);
            ffma2(acc2[0][2], a01.x, bd2); ffma2(acc2[0][3], a01.x, bd3);
            ffma2(acc2[1][0], a01.y, bd0); ffma2(acc2[1][1], a01.y, bd1);
            ffma2(acc2[1][2], a01.y, bd2); ffma2(acc2[1][3], a01.y, bd3);
            ffma2(acc2[2][0], a23.x, bd0); ffma2(acc2[2][1], a23.x, bd1);
            ffma2(acc2[2][2], a23.x, bd2); ffma2(acc2[2][3], a23.x, bd3);
            ffma2(acc2[3][0], a23.y, bd0); ffma2(acc2[3][1], a23.y, bd1);
            ffma2(acc2[3][2], a23.y, bd2); ffma2(acc2[3][3], a23.y, bd3);
        }
        __syncthreads();
    }

#pragma unroll
    for (int p = 0; p < 4; p++) {
        float lo[4], hi[4];
#pragma unroll
        for (int j = 0; j < 4; j++) f2unpack(acc2[p][j], lo[j], hi[j]);
#pragma unroll
        for (int hlf = 0; hlf < 2; hlf++) {
            int r = r0 + tm * 8 + 2 * p + hlf;
            int b = r >> 10;
            int g = r & (GG - 1);
            float* s = hlf ? hi : lo;
            float4 o4 = make_float4(s[0], s[1], s[2], s[3]);
            *(float4*)(outbuf + (((b * HH + hh) * GG + g) * DD) + tn * 4) = o4;
        }
    }
}

// ---------------------------------------------------------------------------
// Flash attention, split-reduction FFMA2 design.
// CTA: q-tile 128 x k-tile 64, 128 threads. Thread grid 16x8:
//   tm = tid>>3 (0..15) -> rows tm*8..+7 ; tn = tid&7 (0..7) -> cols tn*8..+7
// S phase : s2[8][8] packed (even-d, odd-d) partials; operands are contiguous
//           pairs from interleaved Qs2/Ks2 -> 64 ffma2 per 8 LDS.128, no dups.
// softmax : per-row, width-8 shuffles; P written transposed to Pt[j][i].
// PV      : o2[8][4] packed along n (pairs free from natural V rows),
//           P scalar broadcast from Pt rows.
// ---------------------------------------------------------------------------
__global__ __launch_bounds__(128) void attn_kernel(
    const int* __restrict__ mask,
    float* __restrict__ out)
{
    extern __shared__ float sm[];

    const int q0 = blockIdx.x * QT;
    const int bh = blockIdx.y;

    const float* qb = g_q + (size_t)bh * GG * DD;
    const float* kb = g_k + (size_t)bh * GG * DD;
    const float* vb = g_v + (size_t)bh * GG * DD;

    const int tid = threadIdx.x;
    const int tm = tid >> 3;          // 0..15
    const int tn = tid & 7;           // 0..7

    // ---- load Q tile into interleaved layout Qs2[dp][i*2+p] ----
#pragma unroll
    for (int t = 0; t < 16; t++) {
        int id  = tid + t * 128;
        int row = id >> 4;            // 0..127
        int d4  = (id & 15) << 2;     // 0..60
        float4 v = *(const float4*)(qb + (size_t)(q0 + row) * DD + d4);
        int dp0 = d4 >> 1;            // even
        sm[OFF_Q + (dp0    ) * 256 + row * 2 + 0] = v.x;
        sm[OFF_Q + (dp0    ) * 256 + row * 2 + 1] = v.y;
        sm[OFF_Q + (dp0 + 1) * 256 + row * 2 + 0] = v.z;
        sm[OFF_Q + (dp0 + 1) * 256 + row * 2 + 1] = v.w;
    }

    ull o2[8][4];
    float m[8], l[8];
#pragma unroll
    for (int ii = 0; ii < 8; ii++) {
        m[ii] = -3.0e38f;
        l[ii] = 0.f;
#pragma unroll
        for (int jj = 0; jj < 4; jj++) o2[ii][jj] = 0ull;
    }
    const float scale = 0.125f;

    for (int k0 = 0; k0 < GG; k0 += KT) {
        __syncthreads();
        // ---- fill K (interleaved) + V (natural) ----
#pragma unroll
        for (int t = 0; t < 8; t++) {
            int id = tid + t * 128;
            int j  = id >> 4;         // 0..63
            int d4 = (id & 15) << 2;
            float4 kv = *(const float4*)(kb + (size_t)(k0 + j) * DD + d4);
            int dp0 = d4 >> 1;
            sm[OFF_K + (dp0    ) * 128 + j * 2 + 0] = kv.x;
            sm[OFF_K + (dp0    ) * 128 + j * 2 + 1] = kv.y;
            sm[OFF_K + (dp0 + 1) * 128 + j * 2 + 0] = kv.z;
            sm[OFF_K + (dp0 + 1) * 128 + j * 2 + 1] = kv.w;
            float4 vv = *(const float4*)(vb + (size_t)(k0 + j) * DD + d4);
            *(float4*)(&sm[OFF_V + j * 64 + d4]) = vv;
        }
        __syncthreads();

        // ---- S = Q K^T with split-d packed partials ----
        ull s2[8][8];
#pragma unroll
        for (int ii = 0; ii < 8; ii++)
#pragma unroll
            for (int jj = 0; jj < 8; jj++) s2[ii][jj] = 0ull;

#pragma unroll 8
        for (int dp = 0; dp < 32; dp++) {
            ull a[8], b[8];
            ulonglong2 t0 = *(const ulonglong2*)(&sm[OFF_Q + dp * 256 + tm * 16]);
            ulonglong2 t1 = *(const ulonglong2*)(&sm[OFF_Q + dp * 256 + tm * 16 + 4]);
            ulonglong2 t2 = *(const ulonglong2*)(&sm[OFF_Q + dp * 256 + tm * 16 + 8]);
            ulonglong2 t3 = *(const ulonglong2*)(&sm[OFF_Q + dp * 256 + tm * 16 + 12]);
            a[0]=t0.x; a[1]=t0.y; a[2]=t1.x; a[3]=t1.y;
            a[4]=t2.x; a[5]=t2.y; a[6]=t3.x; a[7]=t3.y;
            ulonglong2 u0 = *(const ulonglong2*)(&sm[OFF_K + dp * 128 + tn * 16]);
            ulonglong2 u1 = *(const ulonglong2*)(&sm[OFF_K + dp * 128 + tn * 16 + 4]);
            ulonglong2 u2 = *(const ulonglong2*)(&sm[OFF_K + dp * 128 + tn * 16 + 8]);
            ulonglong2 u3 = *(const ulonglong2*)(&sm[OFF_K + dp * 128 + tn * 16 + 12]);
            b[0]=u0.x; b[1]=u0.y; b[2]=u1.x; b[3]=u1.y;
            b[4]=u2.x; b[5]=u2.y; b[6]=u3.x; b[7]=u3.y;
#pragma unroll
            for (int ii = 0; ii < 8; ii++)
#pragma unroll
                for (int jj = 0; jj < 8; jj++)
                    ffma2(s2[ii][jj], a[ii], b[jj]);
        }

        // ---- mask + scale + online softmax; write Pt[j][i] ----
#pragma unroll
        for (int ii = 0; ii < 8; ii++) {
            float sv[8];
#pragma unroll
            for (int jj = 0; jj < 8; jj++) {
                float lo, hi;
                f2unpack(s2[ii][jj], lo, hi);
                sv[jj] = lo + hi;
            }
            int qi = q0 + tm * 8 + ii;
            const int* mrow = mask + (size_t)qi * GG + k0 + tn * 8;
            int4 m1 = *(const int4*)mrow;
            int4 m2 = *(const int4*)(mrow + 4);
            sv[0] = m1.x ? NEG_INF : sv[0] * scale;
            sv[1] = m1.y ? NEG_INF : sv[1] * scale;
            sv[2] = m1.z ? NEG_INF : sv[2] * scale;
            sv[3] = m1.w ? NEG_INF : sv[3] * scale;
            sv[4] = m2.x ? NEG_INF : sv[4] * scale;
            sv[5] = m2.y ? NEG_INF : sv[5] * scale;
            sv[6] = m2.z ? NEG_INF : sv[6] * scale;
            sv[7] = m2.w ? NEG_INF : sv[7] * scale;

            float tmax = sv[0];
#pragma unroll
            for (int jj = 1; jj < 8; jj++) tmax = fmaxf(tmax, sv[jj]);
#pragma unroll
            for (int off = 4; off; off >>= 1)
                tmax = fmaxf(tmax, __shfl_xor_sync(0xffffffffu, tmax, off, 8));

            float mn    = fmaxf(m[ii], tmax);
            float alpha = __expf(m[ii] - mn);
            m[ii] = mn;

            float rs = 0.f;
#pragma unroll
            for (int jj = 0; jj < 8; jj++) {
                sv[jj] = __expf(sv[jj] - mn);
                rs += sv[jj];
            }
#pragma unroll
            for (int off = 4; off; off >>= 1)
                rs += __shfl_xor_sync(0xffffffffu, rs, off, 8);

            l[ii] = l[ii] * alpha + rs;
            ull al = f2pack(alpha, alpha);
#pragma unroll
            for (int jj = 0; jj < 4; jj++) o2[ii][jj] = fmul2(o2[ii][jj], al);

#pragma unroll
            for (int c = 0; c < 8; c++)
                sm[OFF_P + (tn * 8 + c) * PT_STRIDE + tm * 8 + ii] = sv[c];
        }
        __syncthreads();

        // ---- O += P @ V : n-pairs free from natural V rows ----
#pragma unroll 4
        for (int j = 0; j < KT; j++) {
            float2 p01 = *(const float2*)(&sm[OFF_P + j * PT_STRIDE + tm * 8]);
            float2 p23 = *(const float2*)(&sm[OFF_P + j * PT_STRIDE + tm * 8 + 2]);
            float2 p45 = *(const float2*)(&sm[OFF_P + j * PT_STRIDE + tm * 8 + 4]);
            float2 p67 = *(const float2*)(&sm[OFF_P + j * PT_STRIDE + tm * 8 + 6]);
            ulonglong2 v01 = *(const ulonglong2*)(&sm[OFF_V + j * 64 + tn * 8]);
            ulonglong2 v23 = *(const ulonglong2*)(&sm[OFF_V + j * 64 + tn * 8 + 4]);
            float pf[8] = {p01.x, p01.y, p23.x, p23.y, p45.x, p45.y, p67.x, p67.y};
#pragma unroll
            for (int ii = 0; ii < 8; ii++) {
                ull pd = f2pack(pf[ii], pf[ii]);
                ffma2(o2[ii][0], pd, v01.x);
                ffma2(o2[ii][1], pd, v01.y);
                ffma2(o2[ii][2], pd, v23.x);
                ffma2(o2[ii][3], pd, v23.y);
            }
        }
    }

    // ---- epilogue ----
#pragma unroll
    for (int ii = 0; ii < 8; ii++) {
        float inv = 1.f / l[ii];
        float f[8];
        f2unpack(o2[ii][0], f[0], f[1]);
        f2unpack(o2[ii][1], f[2], f[3]);
        f2unpack(o2[ii][2], f[4], f[5]);
        f2unpack(o2[ii][3], f[6], f[7]);
        float* orow = out + ((size_t)bh * GG + q0 + tm * 8 + ii) * DD + tn * 8;
        *(float4*)(orow)     = make_float4(f[0]*inv, f[1]*inv, f[2]*inv, f[3]*inv);
        *(float4*)(orow + 4) = make_float4(f[4]*inv, f[5]*inv, f[6]*inv, f[7]*inv);
    }
}

// ---------------------------------------------------------------------------
extern "C" void kernel_launch(void* const* d_in, const int* in_sizes, int n_in,
                              void* d_out, int out_size)
{
    const float* h    = (const float*)d_in[0];
    const int*   mask = (const int*)  d_in[1];
    const float* W_Q  = (const float*)d_in[2];
    const float* W_K  = (const float*)d_in[3];
    const float* W_V  = (const float*)d_in[4];
    float* out = (float*)d_out;

    dim3 pgrid(128, 8);
    proj_kernel<<<pgrid, 256>>>(h, W_Q, 0);
    proj_kernel<<<pgrid, 256>>>(h, W_K, 1);
    proj_kernel<<<pgrid, 256>>>(h, W_V, 2);

    cudaFuncSetAttribute(attn_kernel,
                         cudaFuncAttributeMaxDynamicSharedMemorySize,
                         SM_WORDS * 4);

    dim3 agrid(GG / QT, BB * HH);    // 8 x 128
    attn_kernel<<<agrid, 128, SM_WORDS * 4>>>(mask, out);
}

// round 11
// speedup vs baseline: 1.7596x; 1.7596x over previous
#include <cuda_runtime.h>
#include <cstdint>

#define BB 16
#define HH 8
#define GG 1024
#define II 256
#define DD 64

typedef unsigned long long ull;

// scratch for q, k, v projections: [b][h][g][d]
__device__ float g_q[BB*HH*GG*DD];
__device__ float g_k[BB*HH*GG*DD];
__device__ float g_v[BB*HH*GG*DD];
// packed mask bits: g_mbits[row][w] bit c = mask[row][32w+c] != 0
__device__ uint32_t g_mbits[GG * 32];

// ---- packed f32x2 helpers (projection kernel) ----------------------------
__device__ __forceinline__ ull f2pack(float lo, float hi) {
    ull r; asm("mov.b64 %0, {%1, %2};" : "=l"(r) : "f"(lo), "f"(hi)); return r;
}
__device__ __forceinline__ void f2unpack(ull v, float& lo, float& hi) {
    asm("mov.b64 {%0, %1}, %2;" : "=f"(lo), "=f"(hi) : "l"(v));
}
__device__ __forceinline__ void ffma2(ull& d, ull a, ull b) {
    asm("fma.rn.f32x2 %0, %1, %2, %0;" : "+l"(d) : "l"(a), "l"(b));
}

// ---------------------------------------------------------------------------
// Projection (unchanged, known-good): C[16384x64] = A[16384x256] @ W[h][256x64]
// ---------------------------------------------------------------------------
__global__ __launch_bounds__(256) void proj_kernel(
    const float* __restrict__ A,
    const float* __restrict__ W,
    int which)
{
    __shared__ float As[32][132];
    __shared__ float Bs[32][64];

    float* outbuf = (which == 0) ? g_q : (which == 1) ? g_k : g_v;

    const int hh = blockIdx.y;
    const int r0 = blockIdx.x * 128;
    const float* Wh = W + hh * II * DD;

    const int tid = threadIdx.x;
    const int tm = tid >> 4;
    const int tn = tid & 15;

    ull acc2[4][4];
#pragma unroll
    for (int i = 0; i < 4; i++)
#pragma unroll
        for (int j = 0; j < 4; j++) acc2[i][j] = 0ull;

    for (int k0 = 0; k0 < II; k0 += 32) {
#pragma unroll
        for (int t = 0; t < 4; t++) {
            int id  = tid + t * 256;
            int row = id >> 3;
            int c4  = (id & 7) << 2;
            float4 v = *(const float4*)(A + (r0 + row) * II + k0 + c4);
            As[c4 + 0][row] = v.x;
            As[c4 + 1][row] = v.y;
            As[c4 + 2][row] = v.z;
            As[c4 + 3][row] = v.w;
        }
#pragma unroll
        for (int t = 0; t < 2; t++) {
            int id  = tid + t * 256;
            int row = id >> 4;
            int c4  = (id & 15) << 2;
            *(float4*)(&Bs[row][c4]) = *(const float4*)(Wh + (k0 + row) * DD + c4);
        }
        __syncthreads();

#pragma unroll 8
        for (int kk = 0; kk < 32; kk++) {
            ulonglong2 a01 = *(const ulonglong2*)(&As[kk][tm * 8]);
            ulonglong2 a23 = *(const ulonglong2*)(&As[kk][tm * 8 + 4]);
            float4 b4 = *(const float4*)(&Bs[kk][tn * 4]);
            ull bd0 = f2pack(b4.x, b4.x);
            ull bd1 = f2pack(b4.y, b4.y);
            ull bd2 = f2pack(b4.z, b4.z);
            ull bd3 = f2pack(b4.w, b4.w);
            ffma2(acc2[0][0], a01.x, bd0); ffma2(acc2[0][1], a01.x, bd1);
            ffma2(acc2[0][2], a01.x, bd2); ffma2(acc2[0][3], a01.x, bd3);
            ffma2(acc2[1][0], a01.y, bd0); ffma2(acc2[1][1], a01.y, bd1);
            ffma2(acc2[1][2], a01.y, bd2); ffma2(acc2[1][3], a01.y, bd3);
            ffma2(acc2[2][0], a23.x, bd0); ffma2(acc2[2][1], a23.x, bd1);
            ffma2(acc2[2][2], a23.x, bd2); ffma2(acc2[2][3], a23.x, bd3);
            ffma2(acc2[3][0], a23.y, bd0); ffma2(acc2[3][1], a23.y, bd1);
            ffma2(acc2[3][2], a23.y, bd2); ffma2(acc2[3][3], a23.y, bd3);
        }
        __syncthreads();
    }

#pragma unroll
    for (int p = 0; p < 4; p++) {
        float lo[4], hi[4];
#pragma unroll
        for (int j = 0; j < 4; j++) f2unpack(acc2[p][j], lo[j], hi[j]);
#pragma unroll
        for (int hlf = 0; hlf < 2; hlf++) {
            int r = r0 + tm * 8 + 2 * p + hlf;
            int b = r >> 10;
            int g = r & (GG - 1);
            float* s = hlf ? hi : lo;
            float4 o4 = make_float4(s[0], s[1], s[2], s[3]);
            *(float4*)(outbuf + (((b * HH + hh) * GG + g) * DD) + tn * 4) = o4;
        }
    }
}

// ---------------------------------------------------------------------------
// Mask bit-pack: one uint32 per 32 mask ints
// ---------------------------------------------------------------------------
__global__ __launch_bounds__(256) void maskpack_kernel(const int* __restrict__ mask)
{
    int id = blockIdx.x * 256 + threadIdx.x;       // 0 .. 32767
    const int4* p = (const int4*)(mask + id * 32);
    uint32_t b = 0;
#pragma unroll
    for (int t = 0; t < 8; t++) {
        int4 v = p[t];
        b |= (v.x ? 1u : 0u) << (t * 4 + 0);
        b |= (v.y ? 1u : 0u) << (t * 4 + 1);
        b |= (v.z ? 1u : 0u) << (t * 4 + 2);
        b |= (v.w ? 1u : 0u) << (t * 4 + 3);
    }
    g_mbits[id] = b;
}

// ===========================================================================
// mma.sync tf32 flash attention
// ===========================================================================

__device__ __forceinline__ float tf32_rn(float x) {
    uint32_t u;
    asm("cvt.rna.tf32.f32 %0, %1;" : "=r"(u) : "f"(x));
    return __uint_as_float(u);
}

__device__ __forceinline__ void mma8(float* c, const uint32_t* a,
                                     uint32_t b0, uint32_t b1) {
    asm volatile(
        "mma.sync.aligned.m16n8k8.row.col.f32.tf32.tf32.f32 "
        "{%0,%1,%2,%3}, {%4,%5,%6,%7}, {%8,%9}, {%0,%1,%2,%3};"
        : "+f"(c[0]), "+f"(c[1]), "+f"(c[2]), "+f"(c[3])
        : "r"(a[0]), "r"(a[1]), "r"(a[2]), "r"(a[3]), "r"(b0), "r"(b1));
}

// SMEM word offsets
#define SKH 0                       // K hi : 64 x 68
#define SKL 4352                    // K lo
#define SVH 8704                    // V hi : 64 x 72
#define SVL 13312                   // V lo
#define SP  17920                   // P (and Q staging) : 64 x 68
#define SMB 22272                   // mask bits: 64 x 32 uint32
#define SM_WORDS 24320              // 97280 bytes

#define KS 68                       // K / P / Q stride (conflict-free B frags)
#define VS 72                       // V stride

__global__ __launch_bounds__(128) void attn_mma_kernel(float* __restrict__ out)
{
    extern __shared__ float sm[];
    uint32_t* smMB = (uint32_t*)&sm[SMB];

    const int q0  = blockIdx.x * 64;
    const int bh  = blockIdx.y;
    const int tid = threadIdx.x;
    const int w   = tid >> 5;
    const int lane = tid & 31;
    const int lq = lane >> 2;       // group 0..7
    const int lr = lane & 3;        // thread-in-group 0..3
    const int R  = w * 16;          // warp's row base
    const int mr0 = R + lq;         // this thread's row (c0,c1)
    const int mr1 = mr0 + 8;        // this thread's row (c2,c3)

    const float* qb = g_q + (size_t)bh * GG * DD;
    const float* kb = g_k + (size_t)bh * GG * DD;
    const float* vb = g_v + (size_t)bh * GG * DD;

    // ---- stage Q (scaled by 1/8) into P region, copy mask bits ----
#pragma unroll
    for (int t = 0; t < 8; t++) {
        int id = tid + t * 128;
        int r  = id >> 4;
        int c4 = (id & 15) << 2;
        float4 v = *(const float4*)(qb + (size_t)(q0 + r) * DD + c4);
        v.x *= 0.125f; v.y *= 0.125f; v.z *= 0.125f; v.w *= 0.125f;
        *(float4*)&sm[SP + r * KS + c4] = v;
    }
#pragma unroll
    for (int t = 0; t < 4; t++) {
        int id = tid + t * 128;
        ((uint4*)smMB)[id] = ((const uint4*)(g_mbits + q0 * 32))[id];
    }
    __syncthreads();

    // ---- Q fragments (persistent): hi/lo tf32 ----
    uint32_t qh[8][4], ql[8][4];
#pragma unroll
    for (int sk = 0; sk < 8; sk++)
#pragma unroll
        for (int e = 0; e < 4; e++) {
            int row = R + (e & 1) * 8 + lq;
            int col = sk * 8 + (e >> 1) * 4 + lr;
            float v = sm[SP + row * KS + col];
            float h = tf32_rn(v);
            qh[sk][e] = __float_as_uint(h);
            ql[sk][e] = __float_as_uint(v - h);
        }

    float o[8][4];
#pragma unroll
    for (int nt = 0; nt < 8; nt++)
#pragma unroll
        for (int e = 0; e < 4; e++) o[nt][e] = 0.f;
    float m0 = -1e30f, m1 = -1e30f, l0 = 0.f, l1 = 0.f;

    for (int kt = 0; kt < 16; kt++) {
        __syncthreads();            // K/V/P buffers free
        const float* kbt = kb + (size_t)kt * 64 * DD;
        const float* vbt = vb + (size_t)kt * 64 * DD;
#pragma unroll
        for (int t = 0; t < 8; t++) {
            int id = tid + t * 128;
            int j  = id >> 4;
            int c4 = (id & 15) << 2;
            float4 kv = *(const float4*)(kbt + j * DD + c4);
            float4 h = make_float4(tf32_rn(kv.x), tf32_rn(kv.y),
                                   tf32_rn(kv.z), tf32_rn(kv.w));
            float4 lo = make_float4(kv.x - h.x, kv.y - h.y, kv.z - h.z, kv.w - h.w);
            *(float4*)&sm[SKH + j * KS + c4] = h;
            *(float4*)&sm[SKL + j * KS + c4] = lo;
            float4 vv = *(const float4*)(vbt + j * DD + c4);
            h = make_float4(tf32_rn(vv.x), tf32_rn(vv.y), tf32_rn(vv.z), tf32_rn(vv.w));
            lo = make_float4(vv.x - h.x, vv.y - h.y, vv.z - h.z, vv.w - h.w);
            *(float4*)&sm[SVH + j * VS + c4] = h;
            *(float4*)&sm[SVL + j * VS + c4] = lo;
        }
        __syncthreads();

        // ---- S = Q K^T (3-term tf32) ----
        float s[8][4];
#pragma unroll
        for (int nt = 0; nt < 8; nt++)
#pragma unroll
            for (int e = 0; e < 4; e++) s[nt][e] = 0.f;

#pragma unroll
        for (int sk = 0; sk < 8; sk++) {
#pragma unroll
            for (int nt = 0; nt < 8; nt++) {
                int ka = SKH + (nt * 8 + lq) * KS + sk * 8 + lr;
                uint32_t bh0 = __float_as_uint(sm[ka]);
                uint32_t bh1 = __float_as_uint(sm[ka + 4]);
                uint32_t bl0 = __float_as_uint(sm[ka + (SKL - SKH)]);
                uint32_t bl1 = __float_as_uint(sm[ka + (SKL - SKH) + 4]);
                mma8(s[nt], qh[sk], bh0, bh1);
                mma8(s[nt], qh[sk], bl0, bl1);
                mma8(s[nt], ql[sk], bh0, bh1);
            }
        }

        // ---- mask + online softmax ----
        uint32_t w00 = smMB[mr0 * 32 + 2 * kt], w01 = smMB[mr0 * 32 + 2 * kt + 1];
        uint32_t w10 = smMB[mr1 * 32 + 2 * kt], w11 = smMB[mr1 * 32 + 2 * kt + 1];

        float tm0 = -1e30f, tm1 = -1e30f;
#pragma unroll
        for (int nt = 0; nt < 8; nt++) {
            uint32_t wa = (nt < 4) ? w00 : w01;
            uint32_t wb = (nt < 4) ? w10 : w11;
            int sh = 8 * (nt & 3) + 2 * lr;
            uint32_t ma = (wa >> sh) & 3u;
            uint32_t mb = (wb >> sh) & 3u;
            s[nt][0] = (ma & 1u) ? -1e30f : s[nt][0];
            s[nt][1] = (ma & 2u) ? -1e30f : s[nt][1];
            s[nt][2] = (mb & 1u) ? -1e30f : s[nt][2];
            s[nt][3] = (mb & 2u) ? -1e30f : s[nt][3];
            tm0 = fmaxf(tm0, fmaxf(s[nt][0], s[nt][1]));
            tm1 = fmaxf(tm1, fmaxf(s[nt][2], s[nt][3]));
        }
        tm0 = fmaxf(tm0, __shfl_xor_sync(0xffffffffu, tm0, 1));
        tm0 = fmaxf(tm0, __shfl_xor_sync(0xffffffffu, tm0, 2));
        tm1 = fmaxf(tm1, __shfl_xor_sync(0xffffffffu, tm1, 1));
        tm1 = fmaxf(tm1, __shfl_xor_sync(0xffffffffu, tm1, 2));

        float mn0 = fmaxf(m0, tm0), mn1 = fmaxf(m1, tm1);
        float a0 = __expf(m0 - mn0), a1 = __expf(m1 - mn1);
        m0 = mn0; m1 = mn1;

        float rs0 = 0.f, rs1 = 0.f;
#pragma unroll
        for (int nt = 0; nt < 8; nt++) {
            float p0 = tf32_rn(__expf(s[nt][0] - mn0));
            float p1 = tf32_rn(__expf(s[nt][1] - mn0));
            float p2 = tf32_rn(__expf(s[nt][2] - mn1));
            float p3 = tf32_rn(__expf(s[nt][3] - mn1));
            rs0 += p0 + p1;
            rs1 += p2 + p3;
            *(float2*)&sm[SP + mr0 * KS + nt * 8 + 2 * lr] = make_float2(p0, p1);
            *(float2*)&sm[SP + mr1 * KS + nt * 8 + 2 * lr] = make_float2(p2, p3);
        }
        rs0 += __shfl_xor_sync(0xffffffffu, rs0, 1);
        rs0 += __shfl_xor_sync(0xffffffffu, rs0, 2);
        rs1 += __shfl_xor_sync(0xffffffffu, rs1, 1);
        rs1 += __shfl_xor_sync(0xffffffffu, rs1, 2);
        l0 = l0 * a0 + rs0;
        l1 = l1 * a1 + rs1;
#pragma unroll
        for (int nt = 0; nt < 8; nt++) {
            o[nt][0] *= a0; o[nt][1] *= a0;
            o[nt][2] *= a1; o[nt][3] *= a1;
        }
        __syncwarp();               // P visible warp-wide (own rows only)

        // ---- O += P V (2-term tf32) ----
#pragma unroll
        for (int u = 0; u < 8; u++) {
            uint32_t pa[4];
            pa[0] = __float_as_uint(sm[SP + mr0 * KS + u * 8 + lr]);
            pa[1] = __float_as_uint(sm[SP + mr1 * KS + u * 8 + lr]);
            pa[2] = __float_as_uint(sm[SP + mr0 * KS + u * 8 + 4 + lr]);
            pa[3] = __float_as_uint(sm[SP + mr1 * KS + u * 8 + 4 + lr]);
#pragma unroll
            for (int nt = 0; nt < 8; nt++) {
                int va = SVH + (u * 8 + lr) * VS + nt * 8 + lq;
                uint32_t vh0 = __float_as_uint(sm[va]);
                uint32_t vh1 = __float_as_uint(sm[va + 4 * VS]);
                uint32_t vl0 = __float_as_uint(sm[va + (SVL - SVH)]);
                uint32_t vl1 = __float_as_uint(sm[va + (SVL - SVH) + 4 * VS]);
                mma8(o[nt], pa, vh0, vh1);
                mma8(o[nt], pa, vl0, vl1);
            }
        }
    }

    // ---- epilogue ----
    float i0 = 1.f / l0, i1 = 1.f / l1;
    float* ob = out + ((size_t)bh * GG + q0) * DD;
#pragma unroll
    for (int nt = 0; nt < 8; nt++) {
        *(float2*)&ob[(size_t)mr0 * DD + nt * 8 + 2 * lr] =
            make_float2(o[nt][0] * i0, o[nt][1] * i0);
        *(float2*)&ob[(size_t)mr1 * DD + nt * 8 + 2 * lr] =
            make_float2(o[nt][2] * i1, o[nt][3] * i1);
    }
}

// ---------------------------------------------------------------------------
extern "C" void kernel_launch(void* const* d_in, const int* in_sizes, int n_in,
                              void* d_out, int out_size)
{
    const float* h    = (const float*)d_in[0];
    const int*   mask = (const int*)  d_in[1];
    const float* W_Q  = (const float*)d_in[2];
    const float* W_K  = (const float*)d_in[3];
    const float* W_V  = (const float*)d_in[4];
    float* out = (float*)d_out;

    dim3 pgrid(128, 8);
    proj_kernel<<<pgrid, 256>>>(h, W_Q, 0);
    proj_kernel<<<pgrid, 256>>>(h, W_K, 1);
    proj_kernel<<<pgrid, 256>>>(h, W_V, 2);

    maskpack_kernel<<<128, 256>>>(mask);

    cudaFuncSetAttribute(attn_mma_kernel,
                         cudaFuncAttributeMaxDynamicSharedMemorySize,
                         SM_WORDS * 4);

    dim3 agrid(GG / 64, BB * HH);   // 16 x 128 = 2048 CTAs
    attn_mma_kernel<<<agrid, 128, SM_WORDS * 4>>>(out);
}